// round 10
// baseline (speedup 1.0000x reference)
#include <cuda_runtime.h>
#include <cstdint>

#define BATCH 32768
#define IDIM  128
#define HDIM  256
#define ADIM  32
#define MT    128
#define NT    512
#define NBLK  (BATCH/MT)

// ---- packed scratch (floats) ----
#define XPK   0u
#define H0PK  4194304u
#define H1PK  12582912u
#define W0X   20971520u
#define W0H   21069824u
#define W1X   21266432u
#define W1H   21463040u
#define SCR_TOTAL 21659648u
__device__ float scr[SCR_TOTAL];

#define SMS  260                       // smem row stride (floats)
#define SMEM_MAIN (128*SMS*4)          // 133120 B

static __device__ __forceinline__ float tf32r(float x) {
    float r; asm("cvt.rna.tf32.f32 %0, %1;" : "=f"(r) : "f"(x)); return r;
}
static __device__ __forceinline__ void mma8(float c[4], const uint32_t a[4],
                                            const uint32_t b[2]) {
    asm volatile(
        "mma.sync.aligned.m16n8k8.row.col.f32.tf32.tf32.f32 "
        "{%0,%1,%2,%3},{%4,%5,%6,%7},{%8,%9},{%0,%1,%2,%3};"
        : "+f"(c[0]), "+f"(c[1]), "+f"(c[2]), "+f"(c[3])
        : "r"(a[0]), "r"(a[1]), "r"(a[2]), "r"(a[3]), "r"(b[0]), "r"(b[1]));
}
static __device__ __forceinline__ float sigf(float x) {
    return __fdividef(1.0f, 1.0f + __expf(-x));
}
static __device__ __forceinline__ float tanhff(float x) {
    float ax = fabsf(x), e = __expf(-2.0f * ax);
    return copysignf(__fdividef(1.0f - e, 1.0f + e), x);
}
static __device__ __forceinline__ float gru1(float rp, float zp, float ip,
                                             float hp, float hv) {
    float r = sigf(rp), z = sigf(zp);
    float n = tanhff(ip + r * hp);
    return n + z * (hv - n);
}

// ---------------- pre-kernel: pack weights into fragment order ----------------
__global__ void __launch_bounds__(256)
pack_w(const float* __restrict__ wih0, const float* __restrict__ whh0,
       const float* __restrict__ wih1, const float* __restrict__ whh1)
{
    int i = blockIdx.x * 256 + threadIdx.x;     // global out float4 index
    if (i >= 172032) return;
    const float* src; uint32_t base; int K; int l = i;
    if (l < 24576)                { src = wih0; base = W0X; K = 128; }
    else if ((l -= 24576) < 49152){ src = whh0; base = W0H; K = 256; }
    else if ((l -= 49152) < 49152){ src = wih1; base = W1X; K = 256; }
    else { l -= 49152;              src = whh1; base = W1H; K = 256; }
    int lane = l & 31, blk = l >> 5;
    int KB2 = K >> 4;
    int j  = blk % KB2;
    int nb = (blk / KB2) & 31;
    int g  = blk / (KB2 * 32);
    int gid = lane >> 2, tg = lane & 3;
    int row = g * 256 + nb * 8 + gid;
    const float* wr = src + (size_t)row * K + j * 16 + tg;
    float4 v;
    v.x = tf32r(wr[0]); v.y = tf32r(wr[4]);
    v.z = tf32r(wr[8]); v.w = tf32r(wr[12]);
    ((float4*)(scr + base))[l] = v;
}

// ---------------- pre-kernel: pack A-sources into fragment order ----------------
__global__ void __launch_bounds__(256)
pack_a(const float* __restrict__ x, const float* __restrict__ hin)
{
    extern __shared__ float sb[];
    int bb = blockIdx.x, m = blockIdx.y, tid = threadIdx.x;
    const float* src; uint32_t base; int K;
    if (m == 0)      { src = x;   base = XPK;  K = IDIM; }
    else if (m == 1) { src = hin; base = H0PK; K = HDIM; }
    else             { src = hin + (size_t)BATCH * HDIM; base = H1PK; K = HDIM; }
    src += (size_t)bb * 128 * K;
    const int KQ = K / 4;
    for (int i = tid; i < 128 * KQ; i += 256) {
        int r = i / KQ, c = i % KQ;
        float4 v = ((const float4*)src)[i];
        *(float4*)&sb[r * SMS + c * 4] = v;
    }
    __syncthreads();
    const int KB = K / 8;
    const int nout = 8 * KB * 32;
    float4* outp = (float4*)(scr + base) + (size_t)bb * nout;
    for (int o = tid; o < nout; o += 256) {
        int lane = o & 31, kb = (o >> 5) % KB, mb = (o >> 5) / KB;
        int gid = lane >> 2, tg = lane & 3;
        int r0 = mb * 16 + gid, k = kb * 8 + tg;
        float4 v;
        v.x = tf32r(sb[r0 * SMS + k]);
        v.y = tf32r(sb[(r0 + 8) * SMS + k]);
        v.z = tf32r(sb[r0 * SMS + k + 4]);
        v.w = tf32r(sb[(r0 + 8) * SMS + k + 4]);
        outp[o] = v;
    }
}

#define FRAG(d, v) do { d[0] = __float_as_uint((v).x); d[1] = __float_as_uint((v).y); \
                        d[2] = __float_as_uint((v).z); d[3] = __float_as_uint((v).w); } while (0)

__global__ void __launch_bounds__(NT, 1)
gru_ac_kernel(const float* __restrict__ x,    const float* __restrict__ hin,
              const float* __restrict__ bih0, const float* __restrict__ bhh0,
              const float* __restrict__ bih1, const float* __restrict__ bhh1,
              const float* __restrict__ wp,   const float* __restrict__ bp,
              const float* __restrict__ wv,   const float* __restrict__ bv,
              float* __restrict__ out)
{
    extern __shared__ float h0s[];          // 128 x SMS (tf32 copy of h0)
    const float4* S4 = (const float4*)scr;
    const int tid  = threadIdx.x;
    const int lane = tid & 31;
    const int wid  = tid >> 5;
    const int wm   = wid >> 2;
    const int wn   = wid & 3;
    const int gID  = lane >> 2;
    const int tig  = lane & 3;
    const int bb   = blockIdx.x;
    const int rowbase = bb * MT;

    float* outL  = out;
    float* outV  = out + (size_t)BATCH * ADIM;
    float* hbase = out + (size_t)BATCH * (ADIM + 1);   // [2][B][H]

    for (int layer = 0; layer < 2; ++layer) {
        const float* bih = layer ? bih1 : bih0;
        const float* bhh = layer ? bhh1 : bhh0;
        const float* asrch = hin + (size_t)layer * BATCH * HDIM
                                 + (size_t)rowbase * HDIM;
        float* hdst = hbase + (size_t)layer * BATCH * HDIM
                            + (size_t)rowbase * HDIM;

        for (int q = 0; q < 4; ++q) {
            float aR[2][2][4], aZ[2][2][4], aI[2][2][4], aH[2][2][4];
            #pragma unroll
            for (int t = 0; t < 2; ++t)
                #pragma unroll
                for (int s = 0; s < 2; ++s)
                    #pragma unroll
                    for (int k = 0; k < 4; ++k) {
                        aR[t][s][k] = 0.f; aZ[t][s][k] = 0.f;
                        aI[t][s][k] = 0.f; aH[t][s][k] = 0.f;
                    }
            const int nb0 = q * 8 + wn * 2;

            // gmem-fragment phase; A (unique per warp, L2-latency) is
            // register double-buffered; W (L1-hot, shared across wm) inline.
            auto phase_pk = [&](uint32_t a_base4, int KB2a, uint32_t w_base4,
                                int KB2w, float (*accN)[2][4]) {
                const int KBa = KB2a * 2;
                uint32_t ia0 = a_base4 + (uint32_t)(bb * 8 + wm * 2) * KBa * 32 + lane;
                uint32_t ia1 = ia0 + KBa * 32;
                uint32_t iw[3][2];
                #pragma unroll
                for (int g = 0; g < 3; ++g)
                    #pragma unroll
                    for (int s = 0; s < 2; ++s)
                        iw[g][s] = w_base4
                            + (uint32_t)((g * 32 + nb0 + s) * KB2w) * 32 + lane;
                float4 ac[4];
                ac[0] = S4[ia0];  ac[1] = S4[ia0 + 32];
                ac[2] = S4[ia1];  ac[3] = S4[ia1 + 32];
                for (int j = 0; j < KB2a; ++j) {
                    float4 an[4];
                    if (j + 1 < KB2a) {
                        an[0] = S4[ia0 + (2 * j + 2) * 32];
                        an[1] = S4[ia0 + (2 * j + 3) * 32];
                        an[2] = S4[ia1 + (2 * j + 2) * 32];
                        an[3] = S4[ia1 + (2 * j + 3) * 32];
                    }
                    float4 w_[3][2];
                    #pragma unroll
                    for (int g = 0; g < 3; ++g)
                        #pragma unroll
                        for (int s = 0; s < 2; ++s)
                            w_[g][s] = S4[iw[g][s] + j * 32];
                    uint32_t af[2][2][4];
                    FRAG(af[0][0], ac[0]); FRAG(af[0][1], ac[1]);
                    FRAG(af[1][0], ac[2]); FRAG(af[1][1], ac[3]);
                    #pragma unroll
                    for (int s = 0; s < 2; ++s) {
                        uint32_t bR[2][2], bZ[2][2], bN[2][2];
                        bR[0][0] = __float_as_uint(w_[0][s].x);
                        bR[0][1] = __float_as_uint(w_[0][s].y);
                        bR[1][0] = __float_as_uint(w_[0][s].z);
                        bR[1][1] = __float_as_uint(w_[0][s].w);
                        bZ[0][0] = __float_as_uint(w_[1][s].x);
                        bZ[0][1] = __float_as_uint(w_[1][s].y);
                        bZ[1][0] = __float_as_uint(w_[1][s].z);
                        bZ[1][1] = __float_as_uint(w_[1][s].w);
                        bN[0][0] = __float_as_uint(w_[2][s].x);
                        bN[0][1] = __float_as_uint(w_[2][s].y);
                        bN[1][0] = __float_as_uint(w_[2][s].z);
                        bN[1][1] = __float_as_uint(w_[2][s].w);
                        #pragma unroll
                        for (int h = 0; h < 2; ++h)
                            #pragma unroll
                            for (int t = 0; t < 2; ++t) {
                                mma8(aR[t][s], af[t][h], bR[h]);
                                mma8(aZ[t][s], af[t][h], bZ[h]);
                                mma8(accN[t][s], af[t][h], bN[h]);
                            }
                    }
                    #pragma unroll
                    for (int i = 0; i < 4; ++i) ac[i] = an[i];
                }
            };

            // smem-A phase (layer 1 x-part: A = tf32 h0 in smem, 29cyc LDS)
            auto phase_sm = [&](uint32_t w_base4, float (*accN)[2][4]) {
                uint32_t iw[3][2];
                #pragma unroll
                for (int g = 0; g < 3; ++g)
                    #pragma unroll
                    for (int s = 0; s < 2; ++s)
                        iw[g][s] = w_base4
                            + (uint32_t)((g * 32 + nb0 + s) * 16) * 32 + lane;
                for (int j = 0; j < 16; ++j) {
                    uint32_t af[2][2][4];
                    #pragma unroll
                    for (int t = 0; t < 2; ++t) {
                        const float* hp = &h0s[(wm * 32 + t * 16 + gID) * SMS];
                        #pragma unroll
                        for (int h = 0; h < 2; ++h) {
                            int k = (2 * j + h) * 8 + tig;
                            af[t][h][0] = __float_as_uint(hp[k]);
                            af[t][h][1] = __float_as_uint(hp[8 * SMS + k]);
                            af[t][h][2] = __float_as_uint(hp[k + 4]);
                            af[t][h][3] = __float_as_uint(hp[8 * SMS + k + 4]);
                        }
                    }
                    float4 w_[3][2];
                    #pragma unroll
                    for (int g = 0; g < 3; ++g)
                        #pragma unroll
                        for (int s = 0; s < 2; ++s)
                            w_[g][s] = S4[iw[g][s] + j * 32];
                    #pragma unroll
                    for (int s = 0; s < 2; ++s) {
                        uint32_t bR[2][2], bZ[2][2], bN[2][2];
                        bR[0][0] = __float_as_uint(w_[0][s].x);
                        bR[0][1] = __float_as_uint(w_[0][s].y);
                        bR[1][0] = __float_as_uint(w_[0][s].z);
                        bR[1][1] = __float_as_uint(w_[0][s].w);
                        bZ[0][0] = __float_as_uint(w_[1][s].x);
                        bZ[0][1] = __float_as_uint(w_[1][s].y);
                        bZ[1][0] = __float_as_uint(w_[1][s].z);
                        bZ[1][1] = __float_as_uint(w_[1][s].w);
                        bN[0][0] = __float_as_uint(w_[2][s].x);
                        bN[0][1] = __float_as_uint(w_[2][s].y);
                        bN[1][0] = __float_as_uint(w_[2][s].z);
                        bN[1][1] = __float_as_uint(w_[2][s].w);
                        #pragma unroll
                        for (int h = 0; h < 2; ++h)
                            #pragma unroll
                            for (int t = 0; t < 2; ++t) {
                                mma8(aR[t][s], af[t][h], bR[h]);
                                mma8(aZ[t][s], af[t][h], bZ[h]);
                                mma8(accN[t][s], af[t][h], bN[h]);
                            }
                    }
                }
            };

            if (layer == 0) {
                phase_pk(XPK / 4,  8,  W0X / 4, 8,  aI);   // x part (K=128)
                phase_pk(H0PK / 4, 16, W0H / 4, 16, aH);   // h part (K=256)
            } else {
                phase_sm(W1X / 4, aI);                      // h0 (smem) part
                phase_pk(H1PK / 4, 16, W1H / 4, 16, aH);   // h part (K=256)
            }

            // ---- elementwise GRU gates ----
            #pragma unroll
            for (int s = 0; s < 2; ++s) {
                const int c = q * 64 + wn * 16 + s * 8 + tig * 2;
                float2 bi0 = *(const float2*)&bih[c];
                float2 bh0 = *(const float2*)&bhh[c];
                float2 bi1 = *(const float2*)&bih[256 + c];
                float2 bh1 = *(const float2*)&bhh[256 + c];
                float2 bIv = *(const float2*)&bih[512 + c];
                float2 bHv = *(const float2*)&bhh[512 + c];
                float2 bRv = make_float2(bi0.x + bh0.x, bi0.y + bh0.y);
                float2 bZv = make_float2(bi1.x + bh1.x, bi1.y + bh1.y);
                #pragma unroll
                for (int t = 0; t < 2; ++t) {
                    const int ra = wm * 32 + t * 16 + gID;
                    const int rb = ra + 8;
                    float2 ha = *(const float2*)&asrch[(size_t)ra * HDIM + c];
                    float2 hb = *(const float2*)&asrch[(size_t)rb * HDIM + c];
                    float2 oa, ob;
                    oa.x = gru1(aR[t][s][0] + bRv.x, aZ[t][s][0] + bZv.x,
                                aI[t][s][0] + bIv.x, aH[t][s][0] + bHv.x, ha.x);
                    oa.y = gru1(aR[t][s][1] + bRv.y, aZ[t][s][1] + bZv.y,
                                aI[t][s][1] + bIv.y, aH[t][s][1] + bHv.y, ha.y);
                    ob.x = gru1(aR[t][s][2] + bRv.x, aZ[t][s][2] + bZv.x,
                                aI[t][s][2] + bIv.x, aH[t][s][2] + bHv.x, hb.x);
                    ob.y = gru1(aR[t][s][3] + bRv.y, aZ[t][s][3] + bZv.y,
                                aI[t][s][3] + bIv.y, aH[t][s][3] + bHv.y, hb.y);
                    *(float2*)&hdst[(size_t)ra * HDIM + c] = oa;
                    *(float2*)&hdst[(size_t)rb * HDIM + c] = ob;
                    if (layer == 0) {
                        float2 ta = make_float2(tf32r(oa.x), tf32r(oa.y));
                        float2 tb = make_float2(tf32r(ob.x), tf32r(ob.y));
                        *(float2*)&h0s[ra * SMS + c] = ta;
                        *(float2*)&h0s[rb * SMS + c] = tb;
                    }
                }
            }
        }
        __syncthreads();   // h0s (and hdst) complete before layer 1 / heads
    }

    // heads: logits = h1 @ w_p^T + b_p ; value = h1 @ w_v^T + b_v
    {
        const int row = tid >> 2;
        const int qq  = tid & 3;
        const float* h1r = hbase + (size_t)BATCH * HDIM
                                 + (size_t)(rowbase + row) * HDIM;
        float acc[8];
        #pragma unroll
        for (int a = 0; a < 8; ++a) acc[a] = bp[qq * 8 + a];
        float av = bv[0];
        const float4* h4 = (const float4*)h1r;
        for (int kb = 0; kb < HDIM / 4; ++kb) {
            float4 hv = h4[kb];
            #pragma unroll
            for (int a = 0; a < 8; ++a) {
                const float4 wq =
                    *(const float4*)&wp[(qq * 8 + a) * HDIM + kb * 4];
                acc[a] += hv.x * wq.x + hv.y * wq.y + hv.z * wq.z + hv.w * wq.w;
            }
            if (qq == 0) {
                const float4 wq = *(const float4*)&wv[kb * 4];
                av += hv.x * wq.x + hv.y * wq.y + hv.z * wq.z + hv.w * wq.w;
            }
        }
        #pragma unroll
        for (int a = 0; a < 8; ++a)
            outL[(size_t)(rowbase + row) * ADIM + qq * 8 + a] = acc[a];
        if (qq == 0) outV[rowbase + row] = av;
    }
}

extern "C" void kernel_launch(void* const* d_in, const int* in_sizes, int n_in,
                              void* d_out, int out_size) {
    const float* x    = (const float*)d_in[0];
    const float* hin  = (const float*)d_in[1];
    const float* wih0 = (const float*)d_in[2];
    const float* whh0 = (const float*)d_in[3];
    const float* bih0 = (const float*)d_in[4];
    const float* bhh0 = (const float*)d_in[5];
    const float* wih1 = (const float*)d_in[6];
    const float* whh1 = (const float*)d_in[7];
    const float* bih1 = (const float*)d_in[8];
    const float* bhh1 = (const float*)d_in[9];
    const float* wp   = (const float*)d_in[10];
    const float* bp   = (const float*)d_in[11];
    const float* wv   = (const float*)d_in[12];
    const float* bv   = (const float*)d_in[13];
    float* out = (float*)d_out;

    pack_w<<<672, 256>>>(wih0, whh0, wih1, whh1);

    cudaFuncSetAttribute(pack_a,
                         cudaFuncAttributeMaxDynamicSharedMemorySize, SMEM_MAIN);
    pack_a<<<dim3(NBLK, 3), 256, SMEM_MAIN>>>(x, hin);

    cudaFuncSetAttribute(gru_ac_kernel,
                         cudaFuncAttributeMaxDynamicSharedMemorySize, SMEM_MAIN);
    gru_ac_kernel<<<NBLK, NT, SMEM_MAIN>>>(x, hin, bih0, bhh0, bih1, bhh1,
                                           wp, bp, wv, bv, out);
}

// round 12
// speedup vs baseline: 1.3764x; 1.3764x over previous
#include <cuda_runtime.h>
#include <cuda_fp16.h>
#include <cstdint>

#define BATCH 32768
#define IDIM  128
#define HDIM  256
#define ADIM  32
#define MT    128
#define NT    512
#define NBLK  (BATCH/MT)

// ---- packed fp16 scratch (uint32 units) ----
#define XPK   0u
#define H0PK  2097152u
#define H1PK  6291456u
#define W0X   10485760u
#define W0H   10534912u
#define W1X   10633216u
#define W1H   10731520u
#define SCR_TOTAL 10829824u
__device__ uint32_t scr[SCR_TOTAL];

// uint4 base indices
#define XPK4  (XPK/4)
#define H0PK4 (H0PK/4)
#define H1PK4 (H1PK/4)
#define W0X4  (W0X/4)
#define W0H4  (W0H/4)
#define W1X4  (W1X/4)
#define W1H4  (W1H/4)

static __device__ __forceinline__ uint32_t h2p(float a, float b) {
    __half2 h = __floats2half2_rn(a, b);
    return *reinterpret_cast<uint32_t*>(&h);
}
static __device__ __forceinline__ void mma16(float c[4], const uint32_t a[4],
                                             const uint32_t b[2]) {
    asm volatile(
        "mma.sync.aligned.m16n8k16.row.col.f32.f16.f16.f32 "
        "{%0,%1,%2,%3},{%4,%5,%6,%7},{%8,%9},{%0,%1,%2,%3};"
        : "+f"(c[0]), "+f"(c[1]), "+f"(c[2]), "+f"(c[3])
        : "r"(a[0]), "r"(a[1]), "r"(a[2]), "r"(a[3]), "r"(b[0]), "r"(b[1]));
}
static __device__ __forceinline__ float sigf(float x) {
    return __fdividef(1.0f, 1.0f + __expf(-x));
}
static __device__ __forceinline__ float tanhff(float x) {
    float ax = fabsf(x), e = __expf(-2.0f * ax);
    return copysignf(__fdividef(1.0f - e, 1.0f + e), x);
}
static __device__ __forceinline__ float gru1(float rp, float zp, float ip,
                                             float hp, float hv) {
    float r = sigf(rp), z = sigf(zp);
    float n = tanhff(ip + r * hp);
    return n + z * (hv - n);
}

// ---------- pre-kernel: weights -> fp16 m16n8k16 B-fragment order ----------
__global__ void __launch_bounds__(256)
pack_w(const float* __restrict__ wih0, const float* __restrict__ whh0,
       const float* __restrict__ wih1, const float* __restrict__ whh1)
{
    int i = blockIdx.x * 256 + threadIdx.x;
    if (i >= 86016) return;
    const float* src; uint32_t base4; int K; int l = i;
    if (l < 12288)                 { src = wih0; base4 = W0X4; K = 128; }
    else if ((l -= 12288) < 24576) { src = whh0; base4 = W0H4; K = 256; }
    else if ((l -= 24576) < 24576) { src = wih1; base4 = W1X4; K = 256; }
    else { l -= 24576;               src = whh1; base4 = W1H4; K = 256; }
    const int KB = K >> 4;
    int lane = l & 31, blk = l >> 5;
    int j = blk % KB, pair = (blk / KB) & 15, g = blk / (KB * 16);
    int gid = lane >> 2, tig = lane & 3;
    int n_e = g * 256 + pair * 16 + gid;
    int k0  = 16 * j + 2 * tig;
    const float* pe = src + (size_t)n_e * K + k0;
    const float* po = src + (size_t)(n_e + 8) * K + k0;
    uint4 v;
    v.x = h2p(pe[0], pe[1]); v.y = h2p(pe[8], pe[9]);
    v.z = h2p(po[0], po[1]); v.w = h2p(po[8], po[9]);
    ((uint4*)(scr + 0))[base4 + (uint32_t)l] = v;
}

// ---------- pre-kernel: A-sources -> fp16 m16n8k16 A-fragment order ----------
__global__ void __launch_bounds__(256)
pack_a(const float* __restrict__ x, const float* __restrict__ hin)
{
    int bb = blockIdx.x, m = blockIdx.y, tid = threadIdx.x;
    const float* src; uint32_t base4; int K;
    if (m == 0)      { src = x;   base4 = XPK4;  K = IDIM; }
    else if (m == 1) { src = hin; base4 = H0PK4; K = HDIM; }
    else             { src = hin + (size_t)BATCH * HDIM; base4 = H1PK4; K = HDIM; }
    src += (size_t)bb * 128 * K;
    const int KB = K >> 4;
    const int nout = 8 * KB * 32;
    uint4* outp = (uint4*)(scr + 0) + base4 + (size_t)bb * nout;
    for (int o = tid; o < nout; o += 256) {
        int lane = o & 31, j = (o >> 5) % KB, mb = (o >> 5) / KB;
        int gid = lane >> 2, tig = lane & 3;
        int r0 = mb * 16 + gid, k0 = 16 * j + 2 * tig;
        const float* p0 = src + (size_t)r0 * K + k0;
        const float* p1 = src + (size_t)(r0 + 8) * K + k0;
        uint4 v;
        v.x = h2p(p0[0], p0[1]); v.y = h2p(p1[0], p1[1]);
        v.z = h2p(p0[8], p0[9]); v.w = h2p(p1[8], p1[9]);
        outp[o] = v;
    }
}

#define H0ST 132   // u32 stride per row: 128 data (256 fp16) + 4 pad
#define SMEM_H0 (128 * H0ST * 4)   // 67584 B (dynamic)

__global__ void __launch_bounds__(NT, 1)
gru_ac_kernel(const float* __restrict__ x,    const float* __restrict__ hin,
              const float* __restrict__ bih0, const float* __restrict__ bhh0,
              const float* __restrict__ bih1, const float* __restrict__ bhh1,
              const float* __restrict__ wp,   const float* __restrict__ bp,
              const float* __restrict__ wv,   const float* __restrict__ bv,
              float* __restrict__ out)
{
    extern __shared__ uint32_t h0s[];           // 128 x H0ST fp16x2 h0 copy
    const uint4* S4 = (const uint4*)(scr + 0);
    const int tid  = threadIdx.x;
    const int lane = tid & 31;
    const int wid  = tid >> 5;
    const int wm   = wid >> 2;     // 0..3
    const int wn   = wid & 3;      // 0..3
    const int gID  = lane >> 2;
    const int tig  = lane & 3;
    const int bb   = blockIdx.x;
    const int rowbase = bb * MT;

    float* outL  = out;
    float* outV  = out + (size_t)BATCH * ADIM;
    float* hbase = out + (size_t)BATCH * (ADIM + 1);   // [2][B][H]

    for (int layer = 0; layer < 2; ++layer) {
        const float* bih = layer ? bih1 : bih0;
        const float* bhh = layer ? bhh1 : bhh0;
        const float* asrch = hin + (size_t)layer * BATCH * HDIM
                                 + (size_t)rowbase * HDIM;
        float* hdst = hbase + (size_t)layer * BATCH * HDIM
                            + (size_t)rowbase * HDIM;

        for (int q = 0; q < 4; ++q) {
            float aR[2][2][4], aZ[2][2][4], aI[2][2][4], aH[2][2][4];
            #pragma unroll
            for (int t = 0; t < 2; ++t)
                #pragma unroll
                for (int s = 0; s < 2; ++s)
                    #pragma unroll
                    for (int k = 0; k < 4; ++k) {
                        aR[t][s][k] = 0.f; aZ[t][s][k] = 0.f;
                        aI[t][s][k] = 0.f; aH[t][s][k] = 0.f;
                    }
            const int wpair = q * 4 + wn;

            auto mmastep = [&](const uint32_t af[2][4], const uint4 wv[3],
                               float (*accN)[2][4]) {
                #pragma unroll
                for (int s = 0; s < 2; ++s) {
                    uint32_t bR[2], bZ[2], bN[2];
                    bR[0] = s ? wv[0].z : wv[0].x;
                    bR[1] = s ? wv[0].w : wv[0].y;
                    bZ[0] = s ? wv[1].z : wv[1].x;
                    bZ[1] = s ? wv[1].w : wv[1].y;
                    bN[0] = s ? wv[2].z : wv[2].x;
                    bN[1] = s ? wv[2].w : wv[2].y;
                    #pragma unroll
                    for (int t = 0; t < 2; ++t) {
                        mma16(aR[t][s], af[t], bR);
                        mma16(aZ[t][s], af[t], bZ);
                        mma16(accN[t][s], af[t], bN);
                    }
                }
            };

            auto phase_pk = [&](uint32_t a_base4, uint32_t w_base4, int KB,
                                float (*accN)[2][4]) {
                uint32_t ia0 = a_base4
                    + (uint32_t)((bb * 8 + wm * 2) * KB) * 32 + lane;
                uint32_t ia1 = ia0 + (uint32_t)KB * 32;
                uint32_t iw[3];
                #pragma unroll
                for (int g = 0; g < 3; ++g)
                    iw[g] = w_base4 + (uint32_t)((g * 16 + wpair) * KB) * 32 + lane;
                for (int j = 0; j < KB; ++j) {
                    uint4 a0 = S4[ia0 + j * 32];
                    uint4 a1 = S4[ia1 + j * 32];
                    uint4 wv[3];
                    #pragma unroll
                    for (int g = 0; g < 3; ++g) wv[g] = S4[iw[g] + j * 32];
                    uint32_t af[2][4] = {{a0.x, a0.y, a0.z, a0.w},
                                         {a1.x, a1.y, a1.z, a1.w}};
                    mmastep(af, wv, accN);
                }
            };

            // smem-A phase (layer 1 x-part: A = fp16 h0 in smem)
            auto phase_sm = [&](uint32_t w_base4, float (*accN)[2][4]) {
                uint32_t iw[3];
                #pragma unroll
                for (int g = 0; g < 3; ++g)
                    iw[g] = w_base4 + (uint32_t)((g * 16 + wpair) * 16) * 32 + lane;
                for (int j = 0; j < 16; ++j) {
                    uint32_t af[2][4];
                    #pragma unroll
                    for (int t = 0; t < 2; ++t) {
                        int base = (wm * 32 + t * 16 + gID) * H0ST + tig + 8 * j;
                        af[t][0] = h0s[base];
                        af[t][1] = h0s[base + 8 * H0ST];
                        af[t][2] = h0s[base + 4];
                        af[t][3] = h0s[base + 8 * H0ST + 4];
                    }
                    uint4 wv[3];
                    #pragma unroll
                    for (int g = 0; g < 3; ++g) wv[g] = S4[iw[g] + j * 32];
                    mmastep(af, wv, accN);
                }
            };

            if (layer == 0) {
                phase_pk(XPK4,  W0X4, 8,  aI);   // x part (K=128)
                phase_pk(H0PK4, W0H4, 16, aH);   // h part (K=256)
            } else {
                phase_sm(W1X4, aI);               // h0 (smem fp16) part
                phase_pk(H1PK4, W1H4, 16, aH);   // h part (K=256)
            }

            // ---- elementwise GRU gates ----
            #pragma unroll
            for (int s = 0; s < 2; ++s) {
                const int c = q * 64 + wn * 16 + s * 8 + tig * 2;
                float2 bi0 = *(const float2*)&bih[c];
                float2 bh0 = *(const float2*)&bhh[c];
                float2 bi1 = *(const float2*)&bih[256 + c];
                float2 bh1 = *(const float2*)&bhh[256 + c];
                float2 bIv = *(const float2*)&bih[512 + c];
                float2 bHv = *(const float2*)&bhh[512 + c];
                float2 bRv = make_float2(bi0.x + bh0.x, bi0.y + bh0.y);
                float2 bZv = make_float2(bi1.x + bh1.x, bi1.y + bh1.y);
                #pragma unroll
                for (int t = 0; t < 2; ++t) {
                    const int ra = wm * 32 + t * 16 + gID;
                    const int rb = ra + 8;
                    float2 ha = *(const float2*)&asrch[(size_t)ra * HDIM + c];
                    float2 hb = *(const float2*)&asrch[(size_t)rb * HDIM + c];
                    float2 oa, ob;
                    oa.x = gru1(aR[t][s][0] + bRv.x, aZ[t][s][0] + bZv.x,
                                aI[t][s][0] + bIv.x, aH[t][s][0] + bHv.x, ha.x);
                    oa.y = gru1(aR[t][s][1] + bRv.y, aZ[t][s][1] + bZv.y,
                                aI[t][s][1] + bIv.y, aH[t][s][1] + bHv.y, ha.y);
                    ob.x = gru1(aR[t][s][2] + bRv.x, aZ[t][s][2] + bZv.x,
                                aI[t][s][2] + bIv.x, aH[t][s][2] + bHv.x, hb.x);
                    ob.y = gru1(aR[t][s][3] + bRv.y, aZ[t][s][3] + bZv.y,
                                aI[t][s][3] + bIv.y, aH[t][s][3] + bHv.y, hb.y);
                    *(float2*)&hdst[(size_t)ra * HDIM + c] = oa;
                    *(float2*)&hdst[(size_t)rb * HDIM + c] = ob;
                    if (layer == 0) {
                        h0s[ra * H0ST + (c >> 1)] = h2p(oa.x, oa.y);
                        h0s[rb * H0ST + (c >> 1)] = h2p(ob.x, ob.y);
                    }
                }
            }
        }
        __syncthreads();   // h0s + hdst complete before layer 1 / heads
    }

    // heads: logits = h1 @ w_p^T + b_p ; value = h1 @ w_v^T + b_v
    {
        const int row = tid >> 2;
        const int qq  = tid & 3;
        const float* h1r = hbase + (size_t)BATCH * HDIM
                                 + (size_t)(rowbase + row) * HDIM;
        float acc[8];
        #pragma unroll
        for (int a = 0; a < 8; ++a) acc[a] = bp[qq * 8 + a];
        float av = bv[0];
        const float4* h4 = (const float4*)h1r;
        for (int kb = 0; kb < HDIM / 4; ++kb) {
            float4 hv = h4[kb];
            #pragma unroll
            for (int a = 0; a < 8; ++a) {
                const float4 wq =
                    *(const float4*)&wp[(qq * 8 + a) * HDIM + kb * 4];
                acc[a] += hv.x * wq.x + hv.y * wq.y + hv.z * wq.z + hv.w * wq.w;
            }
            if (qq == 0) {
                const float4 wq = *(const float4*)&wv[kb * 4];
                av += hv.x * wq.x + hv.y * wq.y + hv.z * wq.z + hv.w * wq.w;
            }
        }
        #pragma unroll
        for (int a = 0; a < 8; ++a)
            outL[(size_t)(rowbase + row) * ADIM + qq * 8 + a] = acc[a];
        if (qq == 0) outV[rowbase + row] = av;
    }
}

extern "C" void kernel_launch(void* const* d_in, const int* in_sizes, int n_in,
                              void* d_out, int out_size) {
    const float* x    = (const float*)d_in[0];
    const float* hin  = (const float*)d_in[1];
    const float* wih0 = (const float*)d_in[2];
    const float* whh0 = (const float*)d_in[3];
    const float* bih0 = (const float*)d_in[4];
    const float* bhh0 = (const float*)d_in[5];
    const float* wih1 = (const float*)d_in[6];
    const float* whh1 = (const float*)d_in[7];
    const float* bih1 = (const float*)d_in[8];
    const float* bhh1 = (const float*)d_in[9];
    const float* wp   = (const float*)d_in[10];
    const float* bp   = (const float*)d_in[11];
    const float* wv   = (const float*)d_in[12];
    const float* bv   = (const float*)d_in[13];
    float* out = (float*)d_out;

    pack_w<<<336, 256>>>(wih0, whh0, wih1, whh1);
    pack_a<<<dim3(NBLK, 3), 256>>>(x, hin);

    cudaFuncSetAttribute(gru_ac_kernel,
                         cudaFuncAttributeMaxDynamicSharedMemorySize, SMEM_H0);
    gru_ac_kernel<<<NBLK, NT, SMEM_H0>>>(x, hin, bih0, bhh0, bih1, bhh1,
                                         wp, bp, wv, bv, out);
}

// round 13
// speedup vs baseline: 1.4049x; 1.0207x over previous
#include <cuda_runtime.h>
#include <cuda_fp16.h>
#include <cstdint>

#define BATCH 32768
#define IDIM  128
#define HDIM  256
#define ADIM  32
#define MT    64
#define NT    256
#define NBLK  (BATCH/MT)

// ---- packed fp16 scratch (uint32 units) ----
#define XPK   0u
#define H0PK  2097152u
#define H1PK  6291456u
#define W0X   10485760u
#define W0H   10534912u
#define W1X   10633216u
#define W1H   10731520u
#define SCR_TOTAL 10829824u
__device__ uint32_t scr[SCR_TOTAL];

// uint4 base indices
#define XPK4  (XPK/4)
#define H0PK4 (H0PK/4)
#define H1PK4 (H1PK/4)
#define W0X4  (W0X/4)
#define W0H4  (W0H/4)
#define W1X4  (W1X/4)
#define W1H4  (W1H/4)

static __device__ __forceinline__ uint32_t h2p(float a, float b) {
    __half2 h = __floats2half2_rn(a, b);
    return *reinterpret_cast<uint32_t*>(&h);
}
static __device__ __forceinline__ void mma16(float c[4], const uint32_t a[4],
                                             const uint32_t b[2]) {
    asm volatile(
        "mma.sync.aligned.m16n8k16.row.col.f32.f16.f16.f32 "
        "{%0,%1,%2,%3},{%4,%5,%6,%7},{%8,%9},{%0,%1,%2,%3};"
        : "+f"(c[0]), "+f"(c[1]), "+f"(c[2]), "+f"(c[3])
        : "r"(a[0]), "r"(a[1]), "r"(a[2]), "r"(a[3]), "r"(b[0]), "r"(b[1]));
}
static __device__ __forceinline__ float sigf(float x) {
    return __fdividef(1.0f, 1.0f + __expf(-x));
}
static __device__ __forceinline__ float tanhff(float x) {
    float ax = fabsf(x), e = __expf(-2.0f * ax);
    return copysignf(__fdividef(1.0f - e, 1.0f + e), x);
}
static __device__ __forceinline__ float gru1(float rp, float zp, float ip,
                                             float hp, float hv) {
    float r = sigf(rp), z = sigf(zp);
    float n = tanhff(ip + r * hp);
    return n + z * (hv - n);
}

// ---------- pre-kernel: weights -> fp16 m16n8k16 B-fragment order ----------
__global__ void __launch_bounds__(256)
pack_w(const float* __restrict__ wih0, const float* __restrict__ whh0,
       const float* __restrict__ wih1, const float* __restrict__ whh1)
{
    int i = blockIdx.x * 256 + threadIdx.x;
    if (i >= 86016) return;
    const float* src; uint32_t base4; int K; int l = i;
    if (l < 12288)                 { src = wih0; base4 = W0X4; K = 128; }
    else if ((l -= 12288) < 24576) { src = whh0; base4 = W0H4; K = 256; }
    else if ((l -= 24576) < 24576) { src = wih1; base4 = W1X4; K = 256; }
    else { l -= 24576;               src = whh1; base4 = W1H4; K = 256; }
    const int KB = K >> 4;
    int lane = l & 31, blk = l >> 5;
    int j = blk % KB, pair = (blk / KB) & 15, g = blk / (KB * 16);
    int gid = lane >> 2, tig = lane & 3;
    int n_e = g * 256 + pair * 16 + gid;
    int k0  = 16 * j + 2 * tig;
    const float* pe = src + (size_t)n_e * K + k0;
    const float* po = src + (size_t)(n_e + 8) * K + k0;
    uint4 v;
    v.x = h2p(pe[0], pe[1]); v.y = h2p(pe[8], pe[9]);
    v.z = h2p(po[0], po[1]); v.w = h2p(po[8], po[9]);
    ((uint4*)(scr + 0))[base4 + (uint32_t)l] = v;
}

// ---------- pre-kernel: A-sources -> fp16 m16n8k16 A-fragment order ----------
// (per 128-row block; main kernel's 64-row CTAs index m-tiles globally)
__global__ void __launch_bounds__(256)
pack_a(const float* __restrict__ x, const float* __restrict__ hin)
{
    int bb = blockIdx.x, m = blockIdx.y, tid = threadIdx.x;
    const float* src; uint32_t base4; int K;
    if (m == 0)      { src = x;   base4 = XPK4;  K = IDIM; }
    else if (m == 1) { src = hin; base4 = H0PK4; K = HDIM; }
    else             { src = hin + (size_t)BATCH * HDIM; base4 = H1PK4; K = HDIM; }
    src += (size_t)bb * 128 * K;
    const int KB = K >> 4;
    const int nout = 8 * KB * 32;
    uint4* outp = (uint4*)(scr + 0) + base4 + (size_t)bb * nout;
    for (int o = tid; o < nout; o += 256) {
        int lane = o & 31, j = (o >> 5) % KB, mb = (o >> 5) / KB;
        int gid = lane >> 2, tig = lane & 3;
        int r0 = mb * 16 + gid, k0 = 16 * j + 2 * tig;
        const float* p0 = src + (size_t)r0 * K + k0;
        const float* p1 = src + (size_t)(r0 + 8) * K + k0;
        uint4 v;
        v.x = h2p(p0[0], p0[1]); v.y = h2p(p1[0], p1[1]);
        v.z = h2p(p0[8], p0[9]); v.w = h2p(p1[8], p1[9]);
        outp[o] = v;
    }
}

#define H0ST 132   // u32 stride per row: 128 data (256 fp16) + 4 pad
#define SMEM_H0 (MT * H0ST * 4)   // 33792 B per CTA (dynamic)

__global__ void __launch_bounds__(NT, 2)
gru_ac_kernel(const float* __restrict__ x,    const float* __restrict__ hin,
              const float* __restrict__ bih0, const float* __restrict__ bhh0,
              const float* __restrict__ bih1, const float* __restrict__ bhh1,
              const float* __restrict__ wp,   const float* __restrict__ bp,
              const float* __restrict__ wv,   const float* __restrict__ bv,
              float* __restrict__ out)
{
    extern __shared__ uint32_t h0s[];           // MT x H0ST fp16x2 h0 copy
    const uint4* S4 = (const uint4*)(scr + 0);
    const int tid  = threadIdx.x;
    const int lane = tid & 31;
    const int wid  = tid >> 5;
    const int wm   = wid >> 2;     // 0..1 : 32-row band
    const int wn   = wid & 3;      // 0..3 : 16-col band
    const int gID  = lane >> 2;
    const int tig  = lane & 3;
    const int bb   = blockIdx.x;
    const int rowbase = bb * MT;

    float* outL  = out;
    float* outV  = out + (size_t)BATCH * ADIM;
    float* hbase = out + (size_t)BATCH * (ADIM + 1);   // [2][B][H]

    for (int layer = 0; layer < 2; ++layer) {
        const float* bih = layer ? bih1 : bih0;
        const float* bhh = layer ? bhh1 : bhh0;
        const float* asrch = hin + (size_t)layer * BATCH * HDIM
                                 + (size_t)rowbase * HDIM;
        float* hdst = hbase + (size_t)layer * BATCH * HDIM
                            + (size_t)rowbase * HDIM;

        for (int q = 0; q < 4; ++q) {
            float aR[2][2][4], aZ[2][2][4], aI[2][2][4], aH[2][2][4];
            #pragma unroll
            for (int t = 0; t < 2; ++t)
                #pragma unroll
                for (int s = 0; s < 2; ++s)
                    #pragma unroll
                    for (int k = 0; k < 4; ++k) {
                        aR[t][s][k] = 0.f; aZ[t][s][k] = 0.f;
                        aI[t][s][k] = 0.f; aH[t][s][k] = 0.f;
                    }
            const int wpair = q * 4 + wn;

            auto mmastep = [&](const uint32_t af[2][4], const uint4 wv[3],
                               float (*accN)[2][4]) {
                #pragma unroll
                for (int s = 0; s < 2; ++s) {
                    uint32_t bR[2], bZ[2], bN[2];
                    bR[0] = s ? wv[0].z : wv[0].x;
                    bR[1] = s ? wv[0].w : wv[0].y;
                    bZ[0] = s ? wv[1].z : wv[1].x;
                    bZ[1] = s ? wv[1].w : wv[1].y;
                    bN[0] = s ? wv[2].z : wv[2].x;
                    bN[1] = s ? wv[2].w : wv[2].y;
                    #pragma unroll
                    for (int t = 0; t < 2; ++t) {
                        mma16(aR[t][s], af[t], bR);
                        mma16(aZ[t][s], af[t], bZ);
                        mma16(accN[t][s], af[t], bN);
                    }
                }
            };

            auto phase_pk = [&](uint32_t a_base4, uint32_t w_base4, int KB,
                                float (*accN)[2][4]) {
                // global m-tile index: 4 m-tiles per 64-row CTA block
                uint32_t ia0 = a_base4
                    + (uint32_t)((bb * 4 + wm * 2) * KB) * 32 + lane;
                uint32_t ia1 = ia0 + (uint32_t)KB * 32;
                uint32_t iw[3];
                #pragma unroll
                for (int g = 0; g < 3; ++g)
                    iw[g] = w_base4 + (uint32_t)((g * 16 + wpair) * KB) * 32 + lane;
                for (int j = 0; j < KB; ++j) {
                    uint4 a0 = S4[ia0 + j * 32];
                    uint4 a1 = S4[ia1 + j * 32];
                    uint4 wv[3];
                    #pragma unroll
                    for (int g = 0; g < 3; ++g) wv[g] = S4[iw[g] + j * 32];
                    uint32_t af[2][4] = {{a0.x, a0.y, a0.z, a0.w},
                                         {a1.x, a1.y, a1.z, a1.w}};
                    mmastep(af, wv, accN);
                }
            };

            // smem-A phase (layer 1 x-part: A = fp16 h0 in smem)
            auto phase_sm = [&](uint32_t w_base4, float (*accN)[2][4]) {
                uint32_t iw[3];
                #pragma unroll
                for (int g = 0; g < 3; ++g)
                    iw[g] = w_base4 + (uint32_t)((g * 16 + wpair) * 16) * 32 + lane;
                for (int j = 0; j < 16; ++j) {
                    uint32_t af[2][4];
                    #pragma unroll
                    for (int t = 0; t < 2; ++t) {
                        int base = (wm * 32 + t * 16 + gID) * H0ST + tig + 8 * j;
                        af[t][0] = h0s[base];
                        af[t][1] = h0s[base + 8 * H0ST];
                        af[t][2] = h0s[base + 4];
                        af[t][3] = h0s[base + 8 * H0ST + 4];
                    }
                    uint4 wv[3];
                    #pragma unroll
                    for (int g = 0; g < 3; ++g) wv[g] = S4[iw[g] + j * 32];
                    mmastep(af, wv, accN);
                }
            };

            if (layer == 0) {
                phase_pk(XPK4,  W0X4, 8,  aI);   // x part (K=128)
                phase_pk(H0PK4, W0H4, 16, aH);   // h part (K=256)
            } else {
                phase_sm(W1X4, aI);               // h0 (smem fp16) part
                phase_pk(H1PK4, W1H4, 16, aH);   // h part (K=256)
            }

            // ---- elementwise GRU gates ----
            #pragma unroll
            for (int s = 0; s < 2; ++s) {
                const int c = q * 64 + wn * 16 + s * 8 + tig * 2;
                float2 bi0 = *(const float2*)&bih[c];
                float2 bh0 = *(const float2*)&bhh[c];
                float2 bi1 = *(const float2*)&bih[256 + c];
                float2 bh1 = *(const float2*)&bhh[256 + c];
                float2 bIv = *(const float2*)&bih[512 + c];
                float2 bHv = *(const float2*)&bhh[512 + c];
                float2 bRv = make_float2(bi0.x + bh0.x, bi0.y + bh0.y);
                float2 bZv = make_float2(bi1.x + bh1.x, bi1.y + bh1.y);
                #pragma unroll
                for (int t = 0; t < 2; ++t) {
                    const int ra = wm * 32 + t * 16 + gID;
                    const int rb = ra + 8;
                    float2 ha = *(const float2*)&asrch[(size_t)ra * HDIM + c];
                    float2 hb = *(const float2*)&asrch[(size_t)rb * HDIM + c];
                    float2 oa, ob;
                    oa.x = gru1(aR[t][s][0] + bRv.x, aZ[t][s][0] + bZv.x,
                                aI[t][s][0] + bIv.x, aH[t][s][0] + bHv.x, ha.x);
                    oa.y = gru1(aR[t][s][1] + bRv.y, aZ[t][s][1] + bZv.y,
                                aI[t][s][1] + bIv.y, aH[t][s][1] + bHv.y, ha.y);
                    ob.x = gru1(aR[t][s][2] + bRv.x, aZ[t][s][2] + bZv.x,
                                aI[t][s][2] + bIv.x, aH[t][s][2] + bHv.x, hb.x);
                    ob.y = gru1(aR[t][s][3] + bRv.y, aZ[t][s][3] + bZv.y,
                                aI[t][s][3] + bIv.y, aH[t][s][3] + bHv.y, hb.y);
                    *(float2*)&hdst[(size_t)ra * HDIM + c] = oa;
                    *(float2*)&hdst[(size_t)rb * HDIM + c] = ob;
                    if (layer == 0) {
                        h0s[ra * H0ST + (c >> 1)] = h2p(oa.x, oa.y);
                        h0s[rb * H0ST + (c >> 1)] = h2p(ob.x, ob.y);
                    }
                }
            }
        }
        __syncthreads();   // h0s + hdst complete before layer 1 / heads
    }

    // heads: logits = h1 @ w_p^T + b_p ; value = h1 @ w_v^T + b_v
    {
        const int row = tid >> 2;              // 0..63
        const int qq  = tid & 3;
        const float* h1r = hbase + (size_t)BATCH * HDIM
                                 + (size_t)(rowbase + row) * HDIM;
        float acc[8];
        #pragma unroll
        for (int a = 0; a < 8; ++a) acc[a] = bp[qq * 8 + a];
        float av = bv[0];
        const float4* h4 = (const float4*)h1r;
        for (int kb = 0; kb < HDIM / 4; ++kb) {
            float4 hv = h4[kb];
            #pragma unroll
            for (int a = 0; a < 8; ++a) {
                const float4 wq =
                    *(const float4*)&wp[(qq * 8 + a) * HDIM + kb * 4];
                acc[a] += hv.x * wq.x + hv.y * wq.y + hv.z * wq.z + hv.w * wq.w;
            }
            if (qq == 0) {
                const float4 wq = *(const float4*)&wv[kb * 4];
                av += hv.x * wq.x + hv.y * wq.y + hv.z * wq.z + hv.w * wq.w;
            }
        }
        #pragma unroll
        for (int a = 0; a < 8; ++a)
            outL[(size_t)(rowbase + row) * ADIM + qq * 8 + a] = acc[a];
        if (qq == 0) outV[rowbase + row] = av;
    }
}

extern "C" void kernel_launch(void* const* d_in, const int* in_sizes, int n_in,
                              void* d_out, int out_size) {
    const float* x    = (const float*)d_in[0];
    const float* hin  = (const float*)d_in[1];
    const float* wih0 = (const float*)d_in[2];
    const float* whh0 = (const float*)d_in[3];
    const float* bih0 = (const float*)d_in[4];
    const float* bhh0 = (const float*)d_in[5];
    const float* wih1 = (const float*)d_in[6];
    const float* whh1 = (const float*)d_in[7];
    const float* bih1 = (const float*)d_in[8];
    const float* bhh1 = (const float*)d_in[9];
    const float* wp   = (const float*)d_in[10];
    const float* bp   = (const float*)d_in[11];
    const float* wv   = (const float*)d_in[12];
    const float* bv   = (const float*)d_in[13];
    float* out = (float*)d_out;

    pack_w<<<336, 256>>>(wih0, whh0, wih1, whh1);
    pack_a<<<dim3(BATCH / 128, 3), 256>>>(x, hin);

    cudaFuncSetAttribute(gru_ac_kernel,
                         cudaFuncAttributeMaxDynamicSharedMemorySize, SMEM_H0);
    gru_ac_kernel<<<NBLK, NT, SMEM_H0>>>(x, hin, bih0, bhh0, bih1, bhh1,
                                         wp, bp, wv, bv, out);
}